// round 7
// baseline (speedup 1.0000x reference)
#include <cuda_runtime.h>
#include <cuda_bf16.h>
#include <math.h>

// Problem constants
#define BDIM   8
#define TDIM   2048
#define DDIM   1024
#define EDIM   4
#define KCB    64
#define NTAGS  512
#define G3D    3072   // 3*DDIM

#define SCREEN_MARGIN 0.5f

// -------- scratch (device globals; no allocation allowed) --------
__device__ float g_X   [NTAGS * DDIM];        // gathered h rows per tag
__device__ float g_Gih [NTAGS * G3D];         // W_ih @ x_t + b_ih
__device__ float g_Ghh [(KCB + 1) * G3D];     // W_hh @ c_k + b_hh (row 64: zero state)
__device__ float g_cb  [(KCB + 1) * DDIM];    // codebook + zero row (fp32)
__device__ __nv_bfloat162 g_cbP[512 * KCB];   // transposed bf16: [dimpair][code]
__device__ float g_injT[KCB * DDIM];          // W_inj @ c_k
__device__ float g_cnorm[KCB];                // ||c_k||^2
__device__ float g_commit[BDIM];
__device__ int   g_nupd [BDIM];

// ---- packed fp32x2 helpers (exact fp32 per lane) ----
#define FFMA2(acc, a, bsp) \
    asm("fma.rn.f32x2 %0, %1, %2, %0;" : "+l"(acc) : "l"(a), "l"(bsp))
#define SPLAT2(d, f) \
    asm("mov.b64 %0, {%1, %1};" : "=l"(d) : "r"(__float_as_uint(f)))

// -------- gather h rows for each tag --------
__global__ void gather_x(const float* __restrict__ h,
                         const int* __restrict__ bidx,
                         const int* __restrict__ spos) {
    int t = blockIdx.x;
    int e = threadIdx.x;                       // 256 threads, float4 each
    const float4* src = (const float4*)(h + ((size_t)bidx[t] * TDIM + spos[t]) * DDIM);
    float4* dst = (float4*)(g_X + (size_t)t * DDIM);
    dst[e] = src[e];
}

// -------- codebook copy (+zero row) and norms --------
__global__ void prep_cb(const float* __restrict__ cb) {
    int k = blockIdx.x;            // 0..64
    int tid = threadIdx.x;         // 256
    float part = 0.f;
    for (int e = tid; e < DDIM; e += 256) {
        float v = (k < KCB) ? cb[(size_t)k * DDIM + e] : 0.f;
        g_cb[(size_t)k * DDIM + e] = v;
        part += v * v;
    }
    __shared__ float red[256];
    red[tid] = part;
    __syncthreads();
    for (int s = 128; s > 0; s >>= 1) {
        if (tid < s) red[tid] += red[tid + s];
        __syncthreads();
    }
    if (tid == 0 && k < KCB) g_cnorm[k] = red[0];
}

// -------- transposed bf16 codebook: g_cbP[p*64 + k] = bf162(c_k[2p], c_k[2p+1]) ----
__global__ void prep_cbT(const float* __restrict__ cb) {
    int k = blockIdx.x;            // 0..63
    for (int p = threadIdx.x; p < 512; p += 256)
        g_cbP[p * KCB + k] = __floats2bfloat162_rn(cb[(size_t)k * DDIM + 2 * p],
                                                   cb[(size_t)k * DDIM + 2 * p + 1]);
}

// ============================================================================
// Fused fp32 GEMM (f32x2 packed FMA, double-buffered), 3 problems in 1 grid
// ============================================================================
__global__ __launch_bounds__(128)
void fused_gemm(const float* __restrict__ h,
                const int* __restrict__ bidx, const int* __restrict__ spos,
                const float* __restrict__ W_ih, const float* __restrict__ b_ih,
                const float* __restrict__ W_hh, const float* __restrict__ b_hh,
                const float* __restrict__ W_inj)
{
    __shared__ __align__(16) float As[2][16][68];
    __shared__ __align__(16) float Bs[2][16][68];

    const int b = blockIdx.x;
    const float* Bw;
    const float* bias;
    float* C;
    const float* Abase = nullptr;
    int M, N, bm, bn, mode;
    if (b < 384) {
        mode = 0; M = NTAGS; N = G3D;
        bm = (b / 48) * 64; bn = (b % 48) * 64;
        Bw = W_ih; bias = b_ih; C = g_Gih;
    } else if (b < 480) {
        int t = b - 384;
        mode = 1; M = KCB + 1; N = G3D;
        bm = (t / 48) * 64; bn = (t % 48) * 64;
        Bw = W_hh; bias = b_hh; C = g_Ghh; Abase = g_cb;
    } else {
        int t = b - 480;
        mode = 2; M = KCB; N = DDIM;
        bm = 0; bn = t * 64;
        Bw = W_inj; bias = nullptr; C = g_injT; Abase = g_cb;
    }

    const int tid   = threadIdx.x;
    const int r     = tid >> 1;
    const int halfq = (tid & 1) * 8;

    const float* aRow;
    {
        int gm = bm + r; if (gm > M - 1) gm = M - 1;
        if (mode == 0)
            aRow = h + ((size_t)bidx[gm] * TDIM + spos[gm]) * DDIM;
        else
            aRow = Abase + (size_t)gm * DDIM;
    }
    const float* bRow = Bw + (size_t)(bn + r) * DDIM;

    const int ty = tid >> 4;
    const int tx = tid & 15;

    unsigned long long acc[4][4];
#pragma unroll
    for (int p = 0; p < 4; p++)
#pragma unroll
        for (int j = 0; j < 4; j++) acc[p][j] = 0ull;

    {
        float4 a0 = *(const float4*)(aRow + halfq);
        float4 a1 = *(const float4*)(aRow + halfq + 4);
        float4 v0 = *(const float4*)(bRow + halfq);
        float4 v1 = *(const float4*)(bRow + halfq + 4);
        As[0][halfq + 0][r] = a0.x; As[0][halfq + 1][r] = a0.y;
        As[0][halfq + 2][r] = a0.z; As[0][halfq + 3][r] = a0.w;
        As[0][halfq + 4][r] = a1.x; As[0][halfq + 5][r] = a1.y;
        As[0][halfq + 6][r] = a1.z; As[0][halfq + 7][r] = a1.w;
        Bs[0][halfq + 0][r] = v0.x; Bs[0][halfq + 1][r] = v0.y;
        Bs[0][halfq + 2][r] = v0.z; Bs[0][halfq + 3][r] = v0.w;
        Bs[0][halfq + 4][r] = v1.x; Bs[0][halfq + 5][r] = v1.y;
        Bs[0][halfq + 6][r] = v1.z; Bs[0][halfq + 7][r] = v1.w;
    }
    __syncthreads();

    int buf = 0;
#pragma unroll 1
    for (int k0 = 0; k0 < DDIM; k0 += 16) {
        float4 na0, na1, nb0, nb1;
        const bool more = (k0 + 16) < DDIM;
        if (more) {
            const float* ap = aRow + k0 + 16 + halfq;
            na0 = *(const float4*)(ap);
            na1 = *(const float4*)(ap + 4);
            const float* bp = bRow + k0 + 16 + halfq;
            nb0 = *(const float4*)(bp);
            nb1 = *(const float4*)(bp + 4);
        }

#pragma unroll
        for (int kk = 0; kk < 16; kk++) {
            ulonglong2 aA = *(const ulonglong2*)&As[buf][kk][ty * 8];
            ulonglong2 aB = *(const ulonglong2*)&As[buf][kk][ty * 8 + 4];
            float4 bv = *(const float4*)&Bs[buf][kk][tx * 4];
            unsigned long long s0, s1, s2, s3;
            SPLAT2(s0, bv.x); SPLAT2(s1, bv.y);
            SPLAT2(s2, bv.z); SPLAT2(s3, bv.w);
            FFMA2(acc[0][0], aA.x, s0); FFMA2(acc[0][1], aA.x, s1);
            FFMA2(acc[0][2], aA.x, s2); FFMA2(acc[0][3], aA.x, s3);
            FFMA2(acc[1][0], aA.y, s0); FFMA2(acc[1][1], aA.y, s1);
            FFMA2(acc[1][2], aA.y, s2); FFMA2(acc[1][3], aA.y, s3);
            FFMA2(acc[2][0], aB.x, s0); FFMA2(acc[2][1], aB.x, s1);
            FFMA2(acc[2][2], aB.x, s2); FFMA2(acc[2][3], aB.x, s3);
            FFMA2(acc[3][0], aB.y, s0); FFMA2(acc[3][1], aB.y, s1);
            FFMA2(acc[3][2], aB.y, s2); FFMA2(acc[3][3], aB.y, s3);
        }

        if (more) {
            int nb = buf ^ 1;
            As[nb][halfq + 0][r] = na0.x; As[nb][halfq + 1][r] = na0.y;
            As[nb][halfq + 2][r] = na0.z; As[nb][halfq + 3][r] = na0.w;
            As[nb][halfq + 4][r] = na1.x; As[nb][halfq + 5][r] = na1.y;
            As[nb][halfq + 6][r] = na1.z; As[nb][halfq + 7][r] = na1.w;
            Bs[nb][halfq + 0][r] = nb0.x; Bs[nb][halfq + 1][r] = nb0.y;
            Bs[nb][halfq + 2][r] = nb0.z; Bs[nb][halfq + 3][r] = nb0.w;
            Bs[nb][halfq + 4][r] = nb1.x; Bs[nb][halfq + 5][r] = nb1.y;
            Bs[nb][halfq + 6][r] = nb1.z; Bs[nb][halfq + 7][r] = nb1.w;
        }
        __syncthreads();
        buf ^= 1;
    }

#pragma unroll
    for (int p = 0; p < 4; p++) {
        int gm0 = bm + ty * 8 + 2 * p;
#pragma unroll
        for (int j = 0; j < 4; j++) {
            int gn = bn + tx * 4 + j;
            float add = bias ? bias[gn] : 0.f;
            unsigned long long a = acc[p][j];
            float lo = __uint_as_float((unsigned)(a & 0xffffffffull)) + add;
            float hi = __uint_as_float((unsigned)(a >> 32)) + add;
            if (gm0 < M)     C[(size_t)gm0 * N + gn]       = lo;
            if (gm0 + 1 < M) C[(size_t)(gm0 + 1) * N + gn] = hi;
        }
    }
}

__device__ __forceinline__ float sigmoidf_(float x) { return 1.f / (1.f + expf(-x)); }

// ============================================================================
// serial scan v4: dimension-sliced register screen (z never leaves regs),
// transposed bf16 smem codebook, register-replicated slot table,
// all-warp redundant argmins. 3 barriers per step.
// Dynamic smem: s_cbP[512][64] bf162 (128KB).
// ============================================================================
__global__ __launch_bounds__(1024)
void serial_scan(const int* __restrict__ bidx, const int* __restrict__ spos,
                 const int* __restrict__ tok, const int* __restrict__ ctag,
                 float* __restrict__ out) {
    extern __shared__ __align__(16) __nv_bfloat162 s_cbP[];   // [512][KCB]

    const int b = blockIdx.x;
    const int tid = threadIdx.x;
    const int lane = tid & 31;
    const int w = tid >> 5;

    __shared__ __align__(16) float zbuf[DDIM];
    __shared__ float s_part[32][65];   // [warp][code] partial dots, padded
    __shared__ float s_sd[64];         // screened distances
    __shared__ float s_cn[64];
    __shared__ float s_d[64];          // exact distances (INF if not candidate)
    __shared__ int   sm_b[NTAGS];
    __shared__ int   sm_p[NTAGS];
    __shared__ int   sm_k[NTAGS];
    // schedule
    __shared__ int   s_scan[NTAGS];
    __shared__ short s_t [NTAGS];
    __shared__ short s_p2[NTAGS];
    __shared__ unsigned char s_fl[NTAGS];   // bit0 is_char, bits[1:3) slot_w, bits[3:5) slot_r
    __shared__ unsigned char s_outk[NTAGS]; // chosen code per active step
    __shared__ int   s_nact;

    const int char_tag = ctag ? *ctag : 0;

    if (tid < NTAGS) { sm_b[tid] = bidx[tid]; sm_p[tid] = spos[tid]; sm_k[tid] = tok[tid]; }
    if (tid < 64) s_cn[tid] = g_cnorm[tid];
    // load transposed bf16 codebook into smem (once)
    for (int idx = tid; idx < 512 * KCB; idx += 1024)
        s_cbP[idx] = g_cbP[idx];
    __syncthreads();

    // ---- build active-step schedule (token-id dependent only) ----
    int inb = 0, isch = 0;
    if (tid < NTAGS) {
        inb  = (sm_b[tid] == b) ? 1 : 0;
        isch = (inb && sm_k[tid] == char_tag) ? 1 : 0;
        s_scan[tid] = isch;
    }
    __syncthreads();
    for (int off = 1; off < NTAGS; off <<= 1) {
        int v = 0;
        if (tid < NTAGS) { v = s_scan[tid]; if (tid >= off) v += s_scan[tid - off]; }
        __syncthreads();
        if (tid < NTAGS) s_scan[tid] = v;
        __syncthreads();
    }
    int chars_before = 0, active = 0;
    if (tid < NTAGS) {
        chars_before = s_scan[tid] - isch;
        active = (inb && (isch || chars_before > 0)) ? 1 : 0;
    }
    __syncthreads();
    if (tid < NTAGS) s_scan[tid] = active;
    __syncthreads();
    for (int off = 1; off < NTAGS; off <<= 1) {
        int v = 0;
        if (tid < NTAGS) { v = s_scan[tid]; if (tid >= off) v += s_scan[tid - off]; }
        __syncthreads();
        if (tid < NTAGS) s_scan[tid] = v;
        __syncthreads();
    }
    if (tid < NTAGS && active) {
        int pos = s_scan[tid] - 1;           // compacted index (order preserved)
        s_t [pos] = (short)tid;
        s_p2[pos] = (short)sm_p[tid];
        int act = chars_before;
        int sw = isch ? (act & 3) : ((act - 1) & 3);
        int sr = (act - 1) & 3;
        s_fl[pos] = (unsigned char)(isch | (sw << 1) | (sr << 3));
    }
    if (tid == NTAGS - 1) s_nact = s_scan[NTAGS - 1];
    __syncthreads();

    const int n_act = s_nact;
    float commit_acc = 0.f;

    // register-replicated slot table (identical across all threads)
    int c0r = KCB, c1r = KCB, c2r = KCB, c3r = KCB;

    // ---- prologue prefetch for step 0 ----
    int spec_k = -1;
    float pf_gi0 = 0.f, pf_gi1 = 0.f, pf_gi2 = 0.f, pf_x = 0.f;
    float pf_gh0 = 0.f, pf_gh1 = 0.f, pf_gh2 = 0.f, pf_cur = 0.f;
    if (n_act > 0) {
        int t0 = s_t[0];
        if (s_fl[0] & 1) {
            pf_x = g_X[(size_t)t0 * DDIM + tid];
        } else {
            const float* gi = g_Gih + (size_t)t0 * G3D;
            pf_gi0 = gi[tid]; pf_gi1 = gi[1024 + tid]; pf_gi2 = gi[2048 + tid];
        }
    }

    for (int i = 0; i < n_act; i++) {
        const unsigned fl = s_fl[i];
        const bool is_char = (fl & 1) != 0;
        const int  sw = (fl >> 1) & 3;
        const int  sr = (fl >> 3) & 3;
        const int  cur_k = is_char ? 0
                         : (sr == 0 ? c0r : sr == 1 ? c1r : sr == 2 ? c2r : c3r);

        // ---- phase A: compute z (register), store fp32 copy, prefetch next ----
        float zv;
        if (is_char) {
            zv = pf_x;
        } else {
            float gh0, gh1, gh2, cur;
            if (cur_k == spec_k) {
                gh0 = pf_gh0; gh1 = pf_gh1; gh2 = pf_gh2; cur = pf_cur;
            } else {
                const float* gh = g_Ghh + (size_t)cur_k * G3D;
                gh0 = gh[tid]; gh1 = gh[1024 + tid]; gh2 = gh[2048 + tid];
                cur = g_cb[(size_t)cur_k * DDIM + tid];
            }
            float rr = sigmoidf_(pf_gi0 + gh0);
            float zg = sigmoidf_(pf_gi1 + gh1);
            float nn = tanhf(pf_gi2 + rr * gh2);
            zv = (1.f - zg) * nn + zg * cur;
        }
        zbuf[tid] = zv;
        if (i + 1 < n_act) {
            int t2 = s_t[i + 1];
            if (s_fl[i + 1] & 1) {
                pf_x = g_X[(size_t)t2 * DDIM + tid];
            } else {
                const float* gi = g_Gih + (size_t)t2 * G3D;
                pf_gi0 = gi[tid]; pf_gi1 = gi[1024 + tid]; pf_gi2 = gi[2048 + tid];
            }
        }

        // ---- phase B: dim-sliced screen (no barrier needed after A) ----
        // warp w covers dims [32w, 32w+32); lane l accumulates codes 2l, 2l+1
        {
            float a0 = 0.f, a1 = 0.f;
#pragma unroll
            for (int it = 0; it < 16; it++) {
                const int p = 16 * w + it;                 // global dimpair
                float z0 = __shfl_sync(0xffffffffu, zv, 2 * it);
                float z1 = __shfl_sync(0xffffffffu, zv, 2 * it + 1);
                uint2 cc = ((const uint2*)(s_cbP + (size_t)p * KCB))[lane];
                float2 ca = __bfloat1622float2(*(const __nv_bfloat162*)&cc.x);
                float2 cbv = __bfloat1622float2(*(const __nv_bfloat162*)&cc.y);
                a0 += z0 * ca.x + z1 * ca.y;
                a1 += z0 * cbv.x + z1 * cbv.y;
            }
            s_part[w][2 * lane]     = a0;
            s_part[w][2 * lane + 1] = a1;
        }
        __syncthreads();                       // sync 1

        // ---- reduce: warp w finalizes codes 2w, 2w+1 ----
        {
            float p0 = s_part[lane][2 * w];
            float p1 = s_part[lane][2 * w + 1];
#pragma unroll
            for (int off = 16; off; off >>= 1) {
                p0 += __shfl_down_sync(0xffffffffu, p0, off);
                p1 += __shfl_down_sync(0xffffffffu, p1, off);
            }
            if (lane == 0) {
                s_sd[2 * w]     = s_cn[2 * w]     - 2.f * p0;
                s_sd[2 * w + 1] = s_cn[2 * w + 1] - 2.f * p1;
            }
        }
        __syncthreads();                       // sync 2

        // ---- phase C (all warps, redundant): screened argmin + flags ----
        float v0 = s_sd[lane];
        float v1 = s_sd[lane + 32];
        float dm = v0; int im = lane;
        if (v1 < dm) { dm = v1; im = lane + 32; }
#pragma unroll
        for (int off = 16; off; off >>= 1) {
            float od = __shfl_xor_sync(0xffffffffu, dm, off);
            int   oi = __shfl_xor_sync(0xffffffffu, im, off);
            if (od < dm || (od == dm && oi < im)) { dm = od; im = oi; }
        }
        const int jb = 2 * w;
        float srcv = (jb < 32) ? v0 : v1;
        float dj0 = __shfl_sync(0xffffffffu, srcv, jb & 31);
        float dj1 = __shfl_sync(0xffffffffu, srcv, (jb & 31) + 1);

        // speculative prefetch of next state row (screen argmin) — issue first
        {
            const float* gh = g_Ghh + (size_t)im * G3D;
            pf_gh0 = gh[tid]; pf_gh1 = gh[1024 + tid]; pf_gh2 = gh[2048 + tid];
            pf_cur = g_cb[(size_t)im * DDIM + tid];
            spec_k = im;
        }

        // ---- phase D: exact fp32 recheck of flagged own codes ----
        {
            const float4* z4 = (const float4*)zbuf;
            const float thr = dm + SCREEN_MARGIN;
#pragma unroll
            for (int jj = 0; jj < 2; jj++) {
                const int j = jb + jj;
                const float dj = jj ? dj1 : dj0;
                float dx = INFINITY;
                if (dj <= thr) {
                    const float4* cr = (const float4*)(g_cb + (size_t)j * DDIM);
                    float acc = 0.f;
#pragma unroll
                    for (int q = 0; q < 8; q++) {
                        float4 c = cr[lane + 32 * q];
                        float4 z = z4[lane + 32 * q];
                        float e0 = z.x - c.x, e1 = z.y - c.y;
                        float e2 = z.z - c.z, e3 = z.w - c.w;
                        acc += e0 * e0 + e1 * e1 + e2 * e2 + e3 * e3;
                    }
#pragma unroll
                    for (int off = 16; off; off >>= 1)
                        acc += __shfl_down_sync(0xffffffffu, acc, off);
                    dx = acc;
                }
                if (lane == 0) s_d[j] = dx;
            }
        }
        __syncthreads();                       // sync 3

        // ---- phase E (all warps, redundant): exact argmin, state update ----
        {
            float e0 = s_d[lane];
            float e1 = s_d[lane + 32];
            float eb = e0; int ib = lane;
            if (e1 < eb) { eb = e1; ib = lane + 32; }
#pragma unroll
            for (int off = 16; off; off >>= 1) {
                float en = __shfl_xor_sync(0xffffffffu, eb, off);
                int   in_ = __shfl_xor_sync(0xffffffffu, ib, off);
                if (en < eb || (en == eb && in_ < ib)) { eb = en; ib = in_; }
            }
            // ib/eb uniform across block
            if (sw == 0) c0r = ib; else if (sw == 1) c1r = ib;
            else if (sw == 2) c2r = ib; else c3r = ib;
            if (tid == 0) {
                s_outk[i] = (unsigned char)ib;
                commit_acc += eb * (1.f / 1024.f);
            }
            if (ib != im) spec_k = -1;   // speculation failed
        }
    }

    if (tid == 0) { g_commit[b] = commit_acc; g_nupd[b] = n_act; }
    __syncthreads();

    // ---- deferred injection flush (last-writer-wins per seq position) ----
    for (int i = w; i < n_act; i += 32) {
        const int p = s_p2[i];
        bool dup = false;
        for (int j = i + 1 + lane; j < n_act; j += 32)
            dup |= (s_p2[j] == p);
        dup = __any_sync(0xffffffffu, dup);
        if (!dup) {
            const int k = s_outk[i];
            const float4* src = (const float4*)(g_injT + (size_t)k * DDIM);
            float4* dst = (float4*)(out + ((size_t)b * TDIM + p) * DDIM);
#pragma unroll
            for (int e = 0; e < 8; e++)
                dst[lane + 32 * e] = src[lane + 32 * e];
        }
    }
}

__global__ void finalize_k(float* out, long long sidx, long long out_size) {
    if (threadIdx.x == 0 && blockIdx.x == 0) {
        float tc = 0.f;
        int nu = 0;
        for (int i = 0; i < BDIM; i++) { tc += g_commit[i]; nu += g_nupd[i]; }
        if (sidx < out_size)
            out[sidx] = tc / (float)(nu > 0 ? nu : 1);
    }
}

extern "C" void kernel_launch(void* const* d_in, const int* in_sizes, int n_in,
                              void* d_out, int out_size) {
    const float* h    = (const float*)d_in[0];
    const int*   bidx = (const int*)d_in[1];
    const int*   spos = (const int*)d_in[2];
    const int*   tok  = (const int*)d_in[3];
    const int*   ctag = nullptr;
    int o = 4;
    if (n_in >= 11) { ctag = (const int*)d_in[4]; o = 5; }
    const float* W_ih  = (const float*)d_in[o + 0];
    const float* W_hh  = (const float*)d_in[o + 1];
    const float* b_ih  = (const float*)d_in[o + 2];
    const float* b_hh  = (const float*)d_in[o + 3];
    const float* cb    = (const float*)d_in[o + 4];
    const float* W_inj = (const float*)d_in[o + 5];
    float* out = (float*)d_out;

    static int smem_set = 0;
    if (!smem_set) {
        cudaFuncSetAttribute(serial_scan,
                             cudaFuncAttributeMaxDynamicSharedMemorySize,
                             512 * KCB * (int)sizeof(__nv_bfloat162));
        smem_set = 1;
    }

    cudaMemsetAsync(out, 0, (size_t)out_size * sizeof(float), 0);
    gather_x<<<NTAGS, 256>>>(h, bidx, spos);
    prep_cb<<<KCB + 1, 256>>>(cb);
    prep_cbT<<<KCB, 256>>>(cb);
    fused_gemm<<<496, 128>>>(h, bidx, spos, W_ih, b_ih, W_hh, b_hh, W_inj);
    serial_scan<<<BDIM, 1024, 512 * KCB * (int)sizeof(__nv_bfloat162)>>>(
        bidx, spos, tok, ctag, out);
    finalize_k<<<1, 32>>>(out, (long long)BDIM * TDIM * DDIM, (long long)out_size);
}